// round 9
// baseline (speedup 1.0000x reference)
#include <cuda_runtime.h>
#include <cstdint>

#define BN  8
#define CIN 64
#define HH  56
#define WW  56
#define HW  (HH*WW)
#define OCM 128

// Scratch offset maps (dy/dx/mask-logit conv outputs)
__device__ float g_om3[BN * 27 * HW];
__device__ float g_om5[BN * 75 * HW];

typedef unsigned long long u64;

__device__ __forceinline__ u64 pack2(float lo, float hi) {
    u64 r; asm("mov.b64 %0, {%1, %2};" : "=l"(r) : "f"(lo), "f"(hi)); return r;
}
__device__ __forceinline__ void ffma2(u64 &d, u64 a, u64 b) {
    asm("fma.rn.f32x2 %0, %1, %2, %0;" : "+l"(d) : "l"(a), "l"(b));
}
__device__ __forceinline__ float2 unpack2(u64 v) {
    float2 f; asm("mov.b64 {%0, %1}, %2;" : "=f"(f.x), "=f"(f.y) : "l"(v)); return f;
}

// ---------------------------------------------------------------------------
// Offset conv (R3/R7 version). One block per (b, row-pair).
// ---------------------------------------------------------------------------
template<int K>
__global__ void __launch_bounds__(256, 2) offset_conv_kernel(
    const float* __restrict__ x, const float* __restrict__ ow,
    const float* __restrict__ ob)
{
    constexpr int K2  = K * K;
    constexpr int P   = K / 2;
    constexpr int OCF = 3 * K2;
    constexpr int NPT = (((OCF + 1) / 2) + 7) & ~7;
    constexpr int NP  = NPT / 8;
    constexpr int R   = K + 1;

    float* __restrict__ om = (K == 3) ? g_om3 : g_om5;

    __shared__ __align__(16) float2 ws2[2][NPT * K2];
    __shared__ float xs[2][R][72];

    const int b    = blockIdx.x / (HH / 2);
    const int yp   = blockIdx.x % (HH / 2);
    const int y0   = yp * 2;
    const int tid  = threadIdx.x;
    const int lane = tid & 31;
    const int g    = tid >> 5;

    u64 acc[NP * 4] = {};

    auto fill = [&](int c, int buf) {
        for (int i = tid; i < NPT * K2; i += 256) {
            int p = i / K2, tap = i - p * K2;
            int o0 = 2 * p, o1 = o0 + 1;
            float w0 = (o0 < OCF) ? ow[(o0 * CIN + c) * K2 + tap] : 0.f;
            float w1 = (o1 < OCF) ? ow[(o1 * CIN + c) * K2 + tap] : 0.f;
            ws2[buf][i] = make_float2(w0, w1);
        }
        for (int i = tid; i < R * 72; i += 256) {
            int r = i / 72, col = i - r * 72;
            int yy = y0 - P + r, xx = col - P;
            float v = 0.f;
            if (yy >= 0 && yy < HH && xx >= 0 && xx < WW)
                v = x[((b * CIN + c) * HH + yy) * WW + xx];
            xs[buf][r][col] = v;
        }
    };

    fill(0, 0);
    __syncthreads();

    for (int c = 0; c < CIN; c++) {
        int cur = c & 1;
        if (c + 1 < CIN) fill(c + 1, cur ^ 1);

        const u64* wrow = (const u64*)(ws2[cur] + g * NP * K2);
#pragma unroll
        for (int tap = 0; tap < K2; tap++) {
            int r = tap / K, dx = tap % K;
            float a0 = xs[cur][r][lane + dx];
            float a1 = xs[cur][r][lane + 32 + dx];
            float b0 = xs[cur][r + 1][lane + dx];
            float b1 = xs[cur][r + 1][lane + 32 + dx];
            u64 xa = pack2(a0, a0), xb_ = pack2(a1, a1);
            u64 xc = pack2(b0, b0), xd = pack2(b1, b1);
#pragma unroll
            for (int j = 0; j < NP; j++) {
                u64 wv = wrow[j * K2 + tap];
                ffma2(acc[4 * j],     xa, wv);
                ffma2(acc[4 * j + 1], xb_, wv);
                ffma2(acc[4 * j + 2], xc, wv);
                ffma2(acc[4 * j + 3], xd, wv);
            }
        }
        __syncthreads();
    }

#pragma unroll
    for (int j = 0; j < NP; j++) {
        int o0 = (g * NP + j) * 2, o1 = o0 + 1;
        float2 v00 = unpack2(acc[4 * j]);
        float2 v01 = unpack2(acc[4 * j + 1]);
        float2 v10 = unpack2(acc[4 * j + 2]);
        float2 v11 = unpack2(acc[4 * j + 3]);
        int px1 = lane + 32;
        if (o0 < OCF) {
            float bb = ob[o0];
            float* p0 = om + ((b * OCF + o0) * HH + y0) * WW;
            p0[lane] = v00.x + bb;
            p0[WW + lane] = v10.x + bb;
            if (px1 < WW) { p0[px1] = v01.x + bb; p0[WW + px1] = v11.x + bb; }
        }
        if (o1 < OCF) {
            float bb = ob[o1];
            float* p1 = om + ((b * OCF + o1) * HH + y0) * WW;
            p1[lane] = v00.y + bb;
            p1[WW + lane] = v10.y + bb;
            if (px1 < WW) { p1[px1] = v01.y + bb; p1[WW + px1] = v11.y + bb; }
        }
    }
}

// ---------------------------------------------------------------------------
// Deformable conv (+ fused 1x1 residual, biases, ReLU).
// One block per (b, y), 256 threads, 3 blocks/SM. R3 compute loop.
// NEW: per-channel x window in smem; bilinear gather via LDS with exact
// LDG fallback for out-of-window samples. Packed 4B corner descriptor.
// Pipeline: xload(c+2) || gather(c+1) || compute(c), one sync per channel.
// ---------------------------------------------------------------------------
template<int K, int CB>
__global__ void __launch_bounds__(256, 3) deform_kernel(
    const float* __restrict__ x,  const float* __restrict__ w,
    const float* __restrict__ bias, const float* __restrict__ subw_g,
    const float* __restrict__ subb, float* __restrict__ out)
{
    constexpr int K2  = K * K;
    constexpr int P   = K / 2;
    constexpr int NPX = K2 * 56;
    constexpr int NIT = (NPX + 255) / 256;
    constexpr int WIT = (64 * K2 + 255) / 256;
    constexpr int NR  = 2 * P + 8;                 // window rows (12 for k5, 10 for k3)

    const float* __restrict__ om = (K == 3) ? g_om3 : g_om5;

    extern __shared__ __align__(16) char smem_raw[];
    float4*   swt  = (float4*)smem_raw;               // [NPX]
    uint32_t* pidx = (uint32_t*)(swt + NPX);          // [NPX] packed corners
    float2*   ws2  = (float2*)(pidx + NPX);           // [2][64*K2]
    float*    cols = (float*)(ws2 + 2 * 64 * K2);     // [2][NPX] tap-major
    float*    xwin = cols + 2 * NPX;                  // [2][NR*56]
    float*    xrow = xwin + 2 * NR * 56;              // [2][64]
    float2*  subw2 = (float2*)(xrow + 128);           // [2][64]

    const int b    = blockIdx.x / HH;
    const int y    = blockIdx.x % HH;
    const int tid  = threadIdx.x;
    const int lane = tid & 31;
    const int g    = tid >> 5;

    const int ylo = max(y - (P + 3), 0);
    const int yhi = min(y + (P + 4), HH - 1);
    const int wlo = ylo * WW;
    const int whi = (yhi + 1) * WW;
    const int wcnt = whi - wlo;

    // ---- Stage A: sampling parameters, once per block ----
    for (int i = tid; i < NPX; i += 256) {
        int tap = i / 56, pxx = i - tap * 56;
        int base = (b * 3 * K2) * HW + y * WW + pxx;
        float dy = om[base + tap * HW];
        float dx = om[base + (K2 + tap) * HW];
        float ml = om[base + (2 * K2 + tap) * HW];
        float m  = 1.f / (1.f + __expf(-ml));
        float sy = (float)(y   + tap / K - P) + dy;
        float sx = (float)(pxx + tap % K - P) + dx;
        float y0f = floorf(sy), x0f = floorf(sx);
        float ty = sy - y0f, tx = sx - x0f;
        int y0 = (int)y0f, x0 = (int)x0f, y1 = y0 + 1, x1 = x0 + 1;
        bool vy0 = (y0 >= 0) && (y0 < HH), vy1 = (y1 >= 0) && (y1 < HH);
        bool vx0 = (x0 >= 0) && (x0 < WW), vx1 = (x1 >= 0) && (x1 < WW);
        float w00 = (vy0 && vx0) ? (1.f - ty) * (1.f - tx) * m : 0.f;
        float w01 = (vy0 && vx1) ? (1.f - ty) * tx * m : 0.f;
        float w10 = (vy1 && vx0) ? ty * (1.f - tx) * m : 0.f;
        float w11 = (vy1 && vx1) ? ty * tx * m : 0.f;
        int cy0 = min(max(y0, 0), HH - 1);
        int cy1 = min(max(y1, 0), HH - 1);
        int cx0 = min(max(x0, 0), WW - 1);
        int cx1 = min(max(x1, 0), WW - 1);
        uint32_t bb  = (uint32_t)(cy0 * WW + cx0);
        uint32_t ddx = (uint32_t)(cx1 - cx0);           // 0 or 1
        uint32_t ddy = (uint32_t)((cy1 - cy0) * WW);    // 0 or 56
        swt [i] = make_float4(w00, w01, w10, w11);
        pidx[i] = bb | (ddx << 16) | (ddy << 18);
    }

    const float* xb = x + (size_t)b * CIN * HW;

    auto xload = [&](int c, int buf) {
        const float* Xc = xb + c * HW + wlo;
        float* xw = xwin + buf * NR * 56;
        for (int i = tid; i < wcnt; i += 256) xw[i] = Xc[i];
    };

    auto fill = [&](int c, int buf) {
        const float* Xc = xb + c * HW;
        const float* xw = xwin + buf * NR * 56;
        float* cb = cols + buf * NPX;
#pragma unroll
        for (int it = 0; it < NIT; it++) {
            int i = tid + it * 256;
            if (i < NPX) {
                uint32_t pv = pidx[i];
                float4 wv = swt[i];
                int base = pv & 0xFFFF;
                int ddx  = (pv >> 16) & 3;
                int ddy  = pv >> 18;
                float v;
                if (base >= wlo && base + ddy + ddx < whi) {
                    const float* p = xw + (base - wlo);
                    v = wv.x * p[0]   + wv.y * p[ddx]
                      + wv.z * p[ddy] + wv.w * p[ddy + ddx];
                } else {
                    v = wv.x * Xc[base]       + wv.y * Xc[base + ddx]
                      + wv.z * Xc[base + ddy] + wv.w * Xc[base + ddy + ddx];
                }
                cb[i] = v;
            }
        }
        float2* wb = ws2 + buf * 64 * K2;
#pragma unroll
        for (int it = 0; it < WIT; it++) {
            int i = tid + it * 256;
            if (i < 64 * K2) {
                int p = i / K2, tap = i - p * K2;
                wb[i] = make_float2(w[(2 * p * CIN + c) * K2 + tap],
                                    w[((2 * p + 1) * CIN + c) * K2 + tap]);
            }
        }
        if (tid < 64) {
            xrow[buf * 64 + tid] = (tid < WW) ? Xc[y * WW + tid] : 0.f;
        } else if (tid < 128) {
            int p = tid - 64;
            subw2[buf * 64 + p] = make_float2(subw_g[2 * p * CIN + c],
                                              subw_g[(2 * p + 1) * CIN + c]);
        }
    };

    xload(0, 0);
    __syncthreads();          // Stage A tables + xwin(0) ready
    fill(0, 0);
    xload(1, 1);
    __syncthreads();

    u64 acc[16] = {};

    for (int c = 0; c < CIN; c++) {
        int cur = c & 1;
        if (c + 2 < CIN) xload(c + 2, cur);        // overwrite xwin(c); gather(c) done last iter
        if (c + 1 < CIN) fill(c + 1, cur ^ 1);     // gather from xwin(c+1)

        const float* cc  = cols + cur * NPX;
        const u64* wrow  = (const u64*)(ws2 + cur * 64 * K2 + g * 8 * K2);
#pragma unroll
        for (int tap = 0; tap < K2; tap++) {
            float c0 = cc[tap * 56 + lane];
            float c1 = cc[tap * 56 + lane + 32];   // lanes >= 24 read junk; outputs discarded
            u64 xa = pack2(c0, c0), xc = pack2(c1, c1);
#pragma unroll
            for (int j = 0; j < 8; j++) {
                u64 wv = wrow[j * K2 + tap];
                ffma2(acc[2 * j],     xa, wv);
                ffma2(acc[2 * j + 1], xc, wv);
            }
        }
        // fused 1x1 residual
        {
            float s0 = xrow[cur * 64 + lane], s1 = xrow[cur * 64 + lane + 32];
            u64 xa = pack2(s0, s0), xc = pack2(s1, s1);
            const u64* srow = (const u64*)(subw2 + cur * 64 + g * 8);
#pragma unroll
            for (int j = 0; j < 8; j++) {
                u64 sv = srow[j];
                ffma2(acc[2 * j],     xa, sv);
                ffma2(acc[2 * j + 1], xc, sv);
            }
        }
        __syncthreads();
    }

#pragma unroll
    for (int j = 0; j < 8; j++) {
        int o0 = g * 16 + 2 * j, o1 = o0 + 1;
        float2 v0 = unpack2(acc[2 * j]);
        float2 v1 = unpack2(acc[2 * j + 1]);
        float bb0 = bias[o0] + subb[o0];
        float bb1 = bias[o1] + subb[o1];
        size_t base0 = ((size_t)b * (2 * OCM) + CB + o0) * HW + y * WW;
        size_t base1 = ((size_t)b * (2 * OCM) + CB + o1) * HW + y * WW;
        out[base0 + lane] = fmaxf(v0.x + bb0, 0.f);
        out[base1 + lane] = fmaxf(v0.y + bb1, 0.f);
        if (lane + 32 < WW) {
            out[base0 + lane + 32] = fmaxf(v1.x + bb0, 0.f);
            out[base1 + lane + 32] = fmaxf(v1.y + bb1, 0.f);
        }
    }
}

static constexpr int deform_smem(int K) {
    int K2 = K * K, NPX = K2 * 56, NR = 2 * (K / 2) + 8;
    return NPX * 16          // swt
         + NPX * 4           // pidx
         + 2 * 64 * K2 * 8   // ws2
         + 2 * NPX * 4       // cols
         + 2 * NR * 56 * 4   // xwin
         + 128 * 4           // xrow
         + 128 * 8;          // subw2
}

// ---------------------------------------------------------------------------
// Side stream + fork/join events (created once at load; no device allocation).
// ---------------------------------------------------------------------------
struct Aux {
    cudaStream_t s1;
    cudaEvent_t  fork, join;
    Aux() {
        cudaStreamCreateWithFlags(&s1, cudaStreamNonBlocking);
        cudaEventCreateWithFlags(&fork, cudaEventDisableTiming);
        cudaEventCreateWithFlags(&join, cudaEventDisableTiming);
    }
};
static Aux g_aux;

extern "C" void kernel_launch(void* const* d_in, const int* in_sizes, int n_in,
                              void* d_out, int out_size)
{
    const float* x   = (const float*)d_in[0];
    const float* w3  = (const float*)d_in[1];
    const float* b3  = (const float*)d_in[2];
    const float* o3w = (const float*)d_in[3];
    const float* o3b = (const float*)d_in[4];
    const float* w5  = (const float*)d_in[5];
    const float* b5  = (const float*)d_in[6];
    const float* o5w = (const float*)d_in[7];
    const float* o5b = (const float*)d_in[8];
    const float* sw  = (const float*)d_in[9];
    const float* sb  = (const float*)d_in[10];
    float* out = (float*)d_out;

    constexpr int SM3 = deform_smem(3);   // ~28.8 KB
    constexpr int SM5 = deform_smem(5);   // ~71.5 KB
    cudaFuncSetAttribute((const void*)deform_kernel<3, 0>,
                         cudaFuncAttributeMaxDynamicSharedMemorySize, SM3);
    cudaFuncSetAttribute((const void*)deform_kernel<5, OCM>,
                         cudaFuncAttributeMaxDynamicSharedMemorySize, SM5);

    dim3 gridO(BN * (HH / 2));
    dim3 gridD(BN * HH);

    cudaEventRecord(g_aux.fork, 0);
    cudaStreamWaitEvent(g_aux.s1, g_aux.fork, 0);

    offset_conv_kernel<3><<<gridO, 256, 0, g_aux.s1>>>(x, o3w, o3b);
    deform_kernel<3, 0  ><<<gridD, 256, SM3, g_aux.s1>>>(x, w3, b3, sw, sb, out);

    offset_conv_kernel<5><<<gridO, 256>>>(x, o5w, o5b);
    deform_kernel<5, OCM><<<gridD, 256, SM5>>>(x, w5, b5, sw, sb, out);

    cudaEventRecord(g_aux.join, g_aux.s1);
    cudaStreamWaitEvent(0, g_aux.join, 0);
}

// round 10
// speedup vs baseline: 1.1010x; 1.1010x over previous
#include <cuda_runtime.h>
#include <cstdint>

#define BN  8
#define CIN 64
#define HH  56
#define WW  56
#define HW  (HH*WW)
#define OCM 128

typedef unsigned long long u64;

__device__ __forceinline__ u64 pack2(float lo, float hi) {
    u64 r; asm("mov.b64 %0, {%1, %2};" : "=l"(r) : "f"(lo), "f"(hi)); return r;
}
__device__ __forceinline__ void ffma2(u64 &d, u64 a, u64 b) {
    asm("fma.rn.f32x2 %0, %1, %2, %0;" : "+l"(d) : "l"(a), "l"(b));
}
__device__ __forceinline__ float2 unpack2(u64 v) {
    float2 f; asm("mov.b64 {%0, %1}, %2;" : "=f"(f.x), "=f"(f.y) : "l"(v)); return f;
}

// ---------------------------------------------------------------------------
// Fused kernel: offset-conv(row y) -> stage A -> deform conv(row y)
// One block per (b, y): 448 blocks, 256 threads, 3 blocks/SM.
// Smem regions are time-multiplexed:
//   region A: off {ows2, oxs}  ->  deform {swt, pidx}
//   region B: om_s             ->  deform {ws2, cols}
//   region C: xrow, subw2      (deform only)
// ---------------------------------------------------------------------------
template<int K, int CB>
__global__ void __launch_bounds__(256, 3) fused_kernel(
    const float* __restrict__ x,
    const float* __restrict__ ow,  const float* __restrict__ ob,
    const float* __restrict__ w,   const float* __restrict__ bias,
    const float* __restrict__ subw_g, const float* __restrict__ subb,
    float* __restrict__ out)
{
    constexpr int K2  = K * K;
    constexpr int P   = K / 2;
    constexpr int OCF = 3 * K2;
    constexpr int NPT = (((OCF + 1) / 2) + 7) & ~7;   // off och-pairs, padded to 8
    constexpr int NP  = NPT / 8;                      // off pairs per warp
    constexpr int NPX = K2 * 56;
    constexpr int NIT = (NPX + 255) / 256;
    constexpr int WIT = (64 * K2 + 255) / 256;

    // smem layout (bytes)
    constexpr int SZA_OFF = NPT * K2 * 16 + 2 * K * 72 * 4;  // ows2 + oxs
    constexpr int SZA_DEF = NPX * 20;                        // swt + pidx
    constexpr int SZA = ((SZA_OFF > SZA_DEF ? SZA_OFF : SZA_DEF) + 15) & ~15;
    constexpr int SZB_OFF = OCF * 64 * 4;                    // om_s
    constexpr int SZB_DEF = 64 * K2 * 16 + NPX * 8;          // ws2 + cols
    constexpr int SZB = ((SZB_OFF > SZB_DEF ? SZB_OFF : SZB_DEF) + 15) & ~15;
    constexpr int OFF_B = SZA;
    constexpr int OFF_C = SZA + SZB;

    extern __shared__ __align__(16) char smem_raw[];

    const int b    = blockIdx.x / HH;
    const int y    = blockIdx.x % HH;
    const int tid  = threadIdx.x;
    const int lane = tid & 31;
    const int g    = tid >> 5;

    const float* xb = x + (size_t)b * CIN * HW;

    // ======================= Phase 0: offset conv (row y) ==================
    {
        float2* ows2 = (float2*)smem_raw;                        // [2][NPT*K2]
        float*  oxs  = (float*)(smem_raw + NPT * K2 * 16);       // [2][K][72]
        float*  om_s = (float*)(smem_raw + OFF_B);               // [OCF*64]

        u64 oacc[NP * 2] = {};

        auto ofill = [&](int c, int buf) {
            for (int i = tid; i < NPT * K2; i += 256) {
                int p = i / K2, tap = i - p * K2;
                int o0 = 2 * p, o1 = o0 + 1;
                float w0 = (o0 < OCF) ? ow[(o0 * CIN + c) * K2 + tap] : 0.f;
                float w1 = (o1 < OCF) ? ow[(o1 * CIN + c) * K2 + tap] : 0.f;
                ows2[buf * NPT * K2 + i] = make_float2(w0, w1);
            }
            for (int i = tid; i < K * 72; i += 256) {
                int r = i / 72, col = i - r * 72;
                int yy = y - P + r, xx = col - P;
                float v = 0.f;
                if (yy >= 0 && yy < HH && xx >= 0 && xx < WW)
                    v = xb[c * HW + yy * WW + xx];
                oxs[buf * K * 72 + i] = v;
            }
        };

        ofill(0, 0);
        __syncthreads();

        for (int c = 0; c < CIN; c++) {
            int cur = c & 1;
            if (c + 1 < CIN) ofill(c + 1, cur ^ 1);

            const u64*  wrow = (const u64*)(ows2 + cur * NPT * K2) + g * NP * K2;
            const float* xr  = oxs + cur * K * 72;
#pragma unroll
            for (int tap = 0; tap < K2; tap++) {
                int r = tap / K, dx = tap % K;
                float a0 = xr[r * 72 + lane + dx];
                float a1 = xr[r * 72 + lane + 32 + dx];
                u64 xa = pack2(a0, a0), xc = pack2(a1, a1);
#pragma unroll
                for (int j = 0; j < NP; j++) {
                    u64 wv = wrow[j * K2 + tap];
                    ffma2(oacc[2 * j],     xa, wv);
                    ffma2(oacc[2 * j + 1], xc, wv);
                }
            }
            __syncthreads();
        }

        // write offset-map row (with bias) into smem om_s
#pragma unroll
        for (int j = 0; j < NP; j++) {
            int o0 = (g * NP + j) * 2, o1 = o0 + 1;
            float2 v0 = unpack2(oacc[2 * j]);       // px lane    : (o0, o1)
            float2 v1 = unpack2(oacc[2 * j + 1]);   // px lane+32
            if (o0 < OCF) {
                float bb = ob[o0];
                om_s[o0 * 64 + lane]      = v0.x + bb;
                om_s[o0 * 64 + lane + 32] = v1.x + bb;
            }
            if (o1 < OCF) {
                float bb = ob[o1];
                om_s[o1 * 64 + lane]      = v0.y + bb;
                om_s[o1 * 64 + lane + 32] = v1.y + bb;
            }
        }
        __syncthreads();
    }

    // ======================= Stage A: sampling tables ======================
    float4*   swt  = (float4*)smem_raw;                    // [NPX]
    uint32_t* pidx = (uint32_t*)(smem_raw + NPX * 16);     // [NPX]
    {
        const float* om_s = (const float*)(smem_raw + OFF_B);
        for (int i = tid; i < NPX; i += 256) {
            int tap = i / 56, pxx = i - tap * 56;
            float dy = om_s[tap * 64 + pxx];
            float dx = om_s[(K2 + tap) * 64 + pxx];
            float ml = om_s[(2 * K2 + tap) * 64 + pxx];
            float m  = 1.f / (1.f + __expf(-ml));
            float sy = (float)(y   + tap / K - P) + dy;
            float sx = (float)(pxx + tap % K - P) + dx;
            float y0f = floorf(sy), x0f = floorf(sx);
            float ty = sy - y0f, tx = sx - x0f;
            int y0 = (int)y0f, x0 = (int)x0f, y1 = y0 + 1, x1 = x0 + 1;
            bool vy0 = (y0 >= 0) && (y0 < HH), vy1 = (y1 >= 0) && (y1 < HH);
            bool vx0 = (x0 >= 0) && (x0 < WW), vx1 = (x1 >= 0) && (x1 < WW);
            float w00 = (vy0 && vx0) ? (1.f - ty) * (1.f - tx) * m : 0.f;
            float w01 = (vy0 && vx1) ? (1.f - ty) * tx * m : 0.f;
            float w10 = (vy1 && vx0) ? ty * (1.f - tx) * m : 0.f;
            float w11 = (vy1 && vx1) ? ty * tx * m : 0.f;
            int cy0 = min(max(y0, 0), HH - 1);
            int cy1 = min(max(y1, 0), HH - 1);
            int cx0 = min(max(x0, 0), WW - 1);
            int cx1 = min(max(x1, 0), WW - 1);
            uint32_t bb  = (uint32_t)(cy0 * WW + cx0);
            uint32_t ddx = (uint32_t)(cx1 - cx0);            // 0 or 1
            uint32_t ddy = (uint32_t)((cy1 - cy0) * WW);     // 0 or 56
            swt [i] = make_float4(w00, w01, w10, w11);
            pidx[i] = bb | (ddx << 16) | (ddy << 18);
        }
    }
    __syncthreads();   // om_s fully consumed; region B is free now

    // ======================= Phase B: deform conv ==========================
    float2* ws2   = (float2*)(smem_raw + OFF_B);                    // [2][64*K2]
    float*  cols  = (float*)(smem_raw + OFF_B + 64 * K2 * 16);      // [2][NPX]
    float*  xrow  = (float*)(smem_raw + OFF_C);                     // [2][64]
    float2* subw2 = (float2*)(smem_raw + OFF_C + 512);              // [2][64]

    auto fill = [&](int c, int buf) {
        const float* Xc = xb + c * HW;
        float* cb = cols + buf * NPX;
#pragma unroll
        for (int it = 0; it < NIT; it++) {
            int i = tid + it * 256;
            if (i < NPX) {
                uint32_t pv = pidx[i];
                float4 wv = swt[i];
                int base = pv & 0xFFFF;
                int ddx  = (pv >> 16) & 3;
                int ddy  = pv >> 18;
                cb[i] = wv.x * Xc[base]       + wv.y * Xc[base + ddx]
                      + wv.z * Xc[base + ddy] + wv.w * Xc[base + ddy + ddx];
            }
        }
        float2* wb = ws2 + buf * 64 * K2;
#pragma unroll
        for (int it = 0; it < WIT; it++) {
            int i = tid + it * 256;
            if (i < 64 * K2) {
                int p = i / K2, tap = i - p * K2;
                wb[i] = make_float2(w[(2 * p * CIN + c) * K2 + tap],
                                    w[((2 * p + 1) * CIN + c) * K2 + tap]);
            }
        }
        if (tid < 64) {
            xrow[buf * 64 + tid] = (tid < WW) ? Xc[y * WW + tid] : 0.f;
        } else if (tid < 128) {
            int p = tid - 64;
            subw2[buf * 64 + p] = make_float2(subw_g[2 * p * CIN + c],
                                              subw_g[(2 * p + 1) * CIN + c]);
        }
    };

    fill(0, 0);
    __syncthreads();

    u64 acc[16] = {};

    for (int c = 0; c < CIN; c++) {
        int cur = c & 1;
        if (c + 1 < CIN) fill(c + 1, cur ^ 1);

        const float* cc  = cols + cur * NPX;
        const u64* wrow  = (const u64*)(ws2 + cur * 64 * K2) + g * 8 * K2;
#pragma unroll
        for (int tap = 0; tap < K2; tap++) {
            float c0 = cc[tap * 56 + lane];
            float c1 = cc[tap * 56 + lane + 32];   // lanes >= 24 read junk; discarded
            u64 xa = pack2(c0, c0), xc = pack2(c1, c1);
#pragma unroll
            for (int j = 0; j < 8; j++) {
                u64 wv = wrow[j * K2 + tap];
                ffma2(acc[2 * j],     xa, wv);
                ffma2(acc[2 * j + 1], xc, wv);
            }
        }
        // fused 1x1 residual
        {
            float s0 = xrow[cur * 64 + lane], s1 = xrow[cur * 64 + lane + 32];
            u64 xa = pack2(s0, s0), xc = pack2(s1, s1);
            const u64* srow = (const u64*)(subw2 + cur * 64) + g * 8;
#pragma unroll
            for (int j = 0; j < 8; j++) {
                u64 sv = srow[j];
                ffma2(acc[2 * j],     xa, sv);
                ffma2(acc[2 * j + 1], xc, sv);
            }
        }
        __syncthreads();
    }

#pragma unroll
    for (int j = 0; j < 8; j++) {
        int o0 = g * 16 + 2 * j, o1 = o0 + 1;
        float2 v0 = unpack2(acc[2 * j]);
        float2 v1 = unpack2(acc[2 * j + 1]);
        float bb0 = bias[o0] + subb[o0];
        float bb1 = bias[o1] + subb[o1];
        size_t base0 = ((size_t)b * (2 * OCM) + CB + o0) * HW + y * WW;
        size_t base1 = ((size_t)b * (2 * OCM) + CB + o1) * HW + y * WW;
        out[base0 + lane] = fmaxf(v0.x + bb0, 0.f);
        out[base1 + lane] = fmaxf(v0.y + bb1, 0.f);
        if (lane + 32 < WW) {
            out[base0 + lane + 32] = fmaxf(v1.x + bb0, 0.f);
            out[base1 + lane + 32] = fmaxf(v1.y + bb1, 0.f);
        }
    }
}

static constexpr int fused_smem(int K) {
    int K2 = K * K, OCF = 3 * K2, NPX = K2 * 56;
    int NPT = (((OCF + 1) / 2) + 7) & ~7;
    int szA_off = NPT * K2 * 16 + 2 * K * 72 * 4;
    int szA_def = NPX * 20;
    int szA = ((szA_off > szA_def ? szA_off : szA_def) + 15) & ~15;
    int szB_off = OCF * 64 * 4;
    int szB_def = 64 * K2 * 16 + NPX * 8;
    int szB = ((szB_off > szB_def ? szB_off : szB_def) + 15) & ~15;
    return szA + szB + 512 + 1024;
}

// ---------------------------------------------------------------------------
// Side stream + fork/join events (created once at load; no device allocation).
// ---------------------------------------------------------------------------
struct Aux {
    cudaStream_t s1;
    cudaEvent_t  fork, join;
    Aux() {
        cudaStreamCreateWithFlags(&s1, cudaStreamNonBlocking);
        cudaEventCreateWithFlags(&fork, cudaEventDisableTiming);
        cudaEventCreateWithFlags(&join, cudaEventDisableTiming);
    }
};
static Aux g_aux;

extern "C" void kernel_launch(void* const* d_in, const int* in_sizes, int n_in,
                              void* d_out, int out_size)
{
    const float* x   = (const float*)d_in[0];
    const float* w3  = (const float*)d_in[1];
    const float* b3  = (const float*)d_in[2];
    const float* o3w = (const float*)d_in[3];
    const float* o3b = (const float*)d_in[4];
    const float* w5  = (const float*)d_in[5];
    const float* b5  = (const float*)d_in[6];
    const float* o5w = (const float*)d_in[7];
    const float* o5b = (const float*)d_in[8];
    const float* sw  = (const float*)d_in[9];
    const float* sb  = (const float*)d_in[10];
    float* out = (float*)d_out;

    constexpr int SM3 = fused_smem(3);   // ~24.8 KB
    constexpr int SM5 = fused_smem(5);   // ~66.3 KB -> 3 blocks/SM
    cudaFuncSetAttribute((const void*)fused_kernel<3, 0>,
                         cudaFuncAttributeMaxDynamicSharedMemorySize, SM3);
    cudaFuncSetAttribute((const void*)fused_kernel<5, OCM>,
                         cudaFuncAttributeMaxDynamicSharedMemorySize, SM5);

    dim3 grid(BN * HH);

    cudaEventRecord(g_aux.fork, 0);
    cudaStreamWaitEvent(g_aux.s1, g_aux.fork, 0);

    fused_kernel<3, 0  ><<<grid, 256, SM3, g_aux.s1>>>(
        x, o3w, o3b, w3, b3, sw, sb, out);
    fused_kernel<5, OCM><<<grid, 256, SM5>>>(
        x, o5w, o5b, w5, b5, sw, sb, out);

    cudaEventRecord(g_aux.join, g_aux.s1);
    cudaStreamWaitEvent(0, g_aux.join, 0);
}